// round 15
// baseline (speedup 1.0000x reference)
#include <cuda_runtime.h>
#include <cuda_bf16.h>

// Problem constants
#define HD   128
#define LNUM 2
#define NN   256
#define EE   10000
#define ETN  11
#define NPAIR (LNUM*ETN)          // 22
#define TOTE (NPAIR*EE)           // 220000
#define NS   10                   // splits per pair
#define GPS  250                  // int4 edge-groups per split (1000 edges)
#define CH   2000                 // float4 columns per fc chunk
#define ROWS_PB 4
#define PRE  384                  // prefetched float4 columns per row (PDL prologue)

// EDGE_TYPES src/dst as node-type ids: 0=SB,1=PQ,2=PV,3=NB
__constant__ int c_src[ETN] = {0,2,3,1,1,1,2,3,2,1,3};
__constant__ int c_dst[ETN] = {1,1,1,3,0,2,3,2,2,1,3};
// P buffer offset per pair p=l*11+t (concat: [SB|PQ|PV|NB], (l,t) order within dst)
__constant__ int c_pairOff[NPAIR] = {
  20000, 30000, 40000, 160000, 0, 100000, 170000, 110000, 120000, 50000, 180000,
  60000, 70000, 80000, 190000, 10000, 130000, 200000, 140000, 150000, 90000, 210000
};
// fc geometry per node type
__constant__ int c_nf4[4]    = {10000, 40000, 30000, 30000};  // fan_in/4
__constant__ int c_poff[4]   = {0, 20000, 100000, 160000};    // P offset (float2 units)
__constant__ int c_chunks[4] = {5, 20, 15, 15};               // nf4/CH
__constant__ int c_bcum[5]   = {0, 640, 3200, 5120, 7040};    // 128*chunks cumulative

// Scratch (device globals; no allocations allowed)
__device__ __align__(16) float g_P[TOTE];
// per-(pair,split) partial segment state: [NPAIR*NS][NN]
__device__ float g_pden[NPAIR*NS*NN];
__device__ float g_pnum[NPAIR*NS*NN];
__device__ int   g_pfirst[NPAIR*NS*NN];
__device__ int   g_cnt[NPAIR];    // zero-initialized; self-resetting per replay

__device__ __forceinline__ const float* selx(int nt, const float* a, const float* b,
                                             const float* c, const float* d) {
    return nt == 0 ? a : (nt == 1 ? b : (nt == 2 ? c : d));
}

// ---------------------------------------------------------------------------
// Edge sweep + fused merge: grid (NS, NPAIR) x 256 threads. Each block handles
// 1000 edges of one pair. Every block fires the PDL trigger at entry so the
// dependent fc grid co-schedules immediately and prefetches W during the edge
// phase. After flushing its per-split partials, the last block of each pair
// (atomic counter) merges the 10 partials, patches g_P at the first-edge
// positions, initializes out with the bias (pairs 0..7), resets the counter.
// ---------------------------------------------------------------------------
__global__ void __launch_bounds__(256) edge_sweep_kernel(
    const float* __restrict__ xSB, const float* __restrict__ xPQ,
    const float* __restrict__ xPV, const float* __restrict__ xNB,
    const int* __restrict__ ei, const float* __restrict__ ea,
    const float* __restrict__ Wq, const float* __restrict__ bq,
    const float* __restrict__ Wk, const float* __restrict__ bk,
    const float* __restrict__ Wv, const float* __restrict__ bv,
    const float* __restrict__ We,
    const float* __restrict__ Ws, const float* __restrict__ bs,
    const float* __restrict__ B0, const float* __restrict__ B1,
    const float* __restrict__ B2, const float* __restrict__ B3,
    float* __restrict__ out) {
    const int split = blockIdx.x;
    const int p = blockIdx.y;
    const int t = p % ETN;
    const int tid = threadIdx.x;

    // Allow the dependent fc kernel to start scheduling NOW (its blocks
    // prefetch W, then gridDependencySynchronize until this grid completes).
    cudaTriggerProgrammaticLaunchCompletion();

    __shared__ float C[23];
    __shared__ float red[4][23];
    __shared__ float sm_den[NN];
    __shared__ float sm_num[NN];
    __shared__ int   sm_first[NN];

    // ---- prefetch this thread's edge data (overlaps coef phase latency) ----
    const int g = split*GPS + tid;          // valid when tid < GPS
    const bool active = (tid < GPS);
    int4 sv, dv;
    float4 eA, eB;
    if (active) {
        const int4* eis4 = (const int4*)(ei + (t*2+0)*EE);
        const int4* eid4 = (const int4*)(ei + (t*2+1)*EE);
        const float4* eat4 = (const float4*)(ea + (size_t)t*EE*2);
        sv = eis4[g];
        dv = eid4[g];
        eA = eat4[g*2+0];
        eB = eat4[g*2+1];
    }

    // ---- coef: collapse H=128 weights to 23 scalars ----
    if (tid < HD) {
        int h = tid;
        float wq0 = Wq[(p*2+0)*HD+h], wq1 = Wq[(p*2+1)*HD+h], bqv = bq[p*HD+h];
        float wk0 = Wk[(p*2+0)*HD+h], wk1 = Wk[(p*2+1)*HD+h], bkv = bk[p*HD+h];
        float we0 = We[(p*2+0)*HD+h], we1 = We[(p*2+1)*HD+h];
        float wv0 = Wv[(p*2+0)*HD+h], wv1 = Wv[(p*2+1)*HD+h], bvv = bv[p*HD+h];
        float ws0 = Ws[(p*2+0)*HD+h], ws1 = Ws[(p*2+1)*HD+h], bsv = bs[p*HD+h];
        float av[3] = {wq0, wq1, bqv};
        float bb[5] = {wk0, wk1, bkv, we0, we1};
        float vals[23];
#pragma unroll
        for (int a = 0; a < 3; a++)
#pragma unroll
            for (int b = 0; b < 5; b++) vals[a*5+b] = av[a]*bb[b];
        vals[15]=wv0; vals[16]=wv1; vals[17]=bvv; vals[18]=we0; vals[19]=we1;
        vals[20]=ws0; vals[21]=ws1; vals[22]=bsv;
        int lane = h & 31, w = h >> 5;
#pragma unroll
        for (int i = 0; i < 23; i++) {
            float v = vals[i];
#pragma unroll
            for (int o = 16; o; o >>= 1) v += __shfl_down_sync(0xffffffffu, v, o);
            if (lane == 0) red[w][i] = v;
        }
    }
    sm_den[tid] = 0.f;
    sm_num[tid] = 0.f;
    sm_first[tid] = 0x7fffffff;
    __syncthreads();
    if (tid < 23) C[tid] = red[0][tid] + red[1][tid] + red[2][tid] + red[3][tid];
    __syncthreads();

    const float* xsrc = selx(c_src[t], xSB, xPQ, xPV, xNB);
    const float* xdst = selx(c_dst[t], xSB, xPQ, xPV, xNB);

    // ---- single sweep over this split's 250 groups (1000 edges) ----
    if (active) {
        int ss[4] = {sv.x, sv.y, sv.z, sv.w};
        int dd[4] = {dv.x, dv.y, dv.z, dv.w};
        float e0[4] = {eA.x, eA.z, eB.x, eB.z};
        float e1[4] = {eA.y, eA.w, eB.y, eB.w};
        float pv[4];
#pragma unroll
        for (int k = 0; k < 4; k++) {
            float2 xsv = *(const float2*)(xsrc + ss[k]*4 + 2);
            float2 xtv = *(const float2*)(xdst + dd[k]*4 + 2);
            float xs0 = xsv.x, xs1 = xsv.y;
            float xt0 = xtv.x, xt1 = xtv.y;
            float r0 = C[0]*xs0 + C[1]*xs1 + C[2] + C[3]*e0[k] + C[4]*e1[k];
            float r1 = C[5]*xs0 + C[6]*xs1 + C[7] + C[8]*e0[k] + C[9]*e1[k];
            float r2 = C[10]*xs0 + C[11]*xs1 + C[12] + C[13]*e0[k] + C[14]*e1[k];
            float logit = (xt0*r0 + xt1*r1 + r2) * 0.08838834764831845f; // 1/sqrt(128)
            float ex = __expf(logit);
            float vs = xs0*C[15] + xs1*C[16] + C[17] + e0[k]*C[18] + e1[k]*C[19];
            atomicAdd(&sm_den[dd[k]], ex);
            atomicAdd(&sm_num[dd[k]], ex * vs);
            atomicMin(&sm_first[dd[k]], g*4 + k);
            pv[k] = xt0*C[20] + xt1*C[21] + C[22];   // skip term only
        }
        ((float4*)(g_P + c_pairOff[p]))[g] = make_float4(pv[0], pv[1], pv[2], pv[3]);
    }
    __syncthreads();

    // ---- flush per-split partials ----
    int base = (p*NS + split)*NN + tid;
    g_pden[base] = sm_den[tid];
    g_pnum[base] = sm_num[tid];
    g_pfirst[base] = sm_first[tid];
    __threadfence();

    // ---- last block of this pair merges ----
    __shared__ int s_last;
    if (tid == 0) s_last = (atomicAdd(&g_cnt[p], 1) == NS - 1);
    __syncthreads();
    if (!s_last) return;
    __threadfence();   // acquire: all pair blocks' partials + g_P stores visible

    {
        int pbase = p*NS*NN + tid;
        float den = 0.f, num = 0.f;
        int first = 0x7fffffff;
#pragma unroll
        for (int sp = 0; sp < NS; sp++) {
            den += g_pden[pbase + sp*NN];
            num += g_pnum[pbase + sp*NN];
            first = min(first, g_pfirst[pbase + sp*NN]);
        }
        if (first != 0x7fffffff)
            g_P[c_pairOff[p] + first] += num / den;
    }
    if (p < 8) {   // init out = bias for this pair's slice of the 2048 outputs
        int i = p*256 + tid;
        int nt = i >> 9, r = i & 511;
        const float* B = selx(nt, B0, B1, B2, B3);
        out[i] = B[r];
    }
    if (tid == 0) g_cnt[p] = 0;    // reset for next graph replay
}

// ---------------------------------------------------------------------------
// FC matvec, split-K with PDL overlap: each block = 4 rows x one 2000-float4
// column chunk. Launched with programmatic stream serialization; the edge
// kernel triggers early, so fc blocks co-schedule during the edge phase,
// prefetch their first PRE columns of W (P-independent, 24.6KB smem) and then
// cudaGridDependencySynchronize() before touching g_P/out. Partials atomicAdd
// directly into out (pre-set to bias). W streamed with __ldcs.
// ---------------------------------------------------------------------------
__global__ void __launch_bounds__(256) fc_kernel(
    const float* __restrict__ W0, const float* __restrict__ W1,
    const float* __restrict__ W2, const float* __restrict__ W3,
    float* __restrict__ out) {
    __shared__ float4 spre[ROWS_PB][PRE];
    int bid = blockIdx.x;
    int nt = 3;
    if (bid < c_bcum[1]) nt = 0;
    else if (bid < c_bcum[2]) nt = 1;
    else if (bid < c_bcum[3]) nt = 2;
    int local = bid - c_bcum[nt];
    int nchunk = c_chunks[nt];
    int rg = local / nchunk;       // 0..127
    int ch = local % nchunk;
    int nf4 = c_nf4[nt];
    int r0 = rg * ROWS_PB;
    const float* W = selx(nt, W0, W1, W2, W3);
    const float4* __restrict__ Wr0 = (const float4*)W + (size_t)(r0+0) * nf4;
    const float4* __restrict__ Wr1 = (const float4*)W + (size_t)(r0+1) * nf4;
    const float4* __restrict__ Wr2 = (const float4*)W + (size_t)(r0+2) * nf4;
    const float4* __restrict__ Wr3 = (const float4*)W + (size_t)(r0+3) * nf4;
    const float2* __restrict__ P2 = (const float2*)(g_P + c_poff[nt]);

    int j0 = ch * CH;
    int j1 = j0 + CH;

    // ---- PDL prologue: prefetch W (no dependency on the edge kernel) ----
#pragma unroll
    for (int jj = threadIdx.x; jj < PRE; jj += 256) {
        int j = j0 + jj;
        spre[0][jj] = __ldcs(&Wr0[j]);
        spre[1][jj] = __ldcs(&Wr1[j]);
        spre[2][jj] = __ldcs(&Wr2[j]);
        spre[3][jj] = __ldcs(&Wr3[j]);
    }
    cudaGridDependencySynchronize();   // wait for edge kernel (g_P, out=bias)

    float a0 = 0.f, a1 = 0.f, a2 = 0.f, a3 = 0.f;
#pragma unroll
    for (int jj = threadIdx.x; jj < PRE; jj += 256) {
        int j = j0 + jj;
        float2 pv = __ldg(&P2[j]);
        float4 w0 = spre[0][jj];
        float4 w1 = spre[1][jj];
        float4 w2 = spre[2][jj];
        float4 w3 = spre[3][jj];
        a0 = fmaf(w0.x, pv.x, fmaf(w0.z, pv.y, a0));
        a1 = fmaf(w1.x, pv.x, fmaf(w1.z, pv.y, a1));
        a2 = fmaf(w2.x, pv.x, fmaf(w2.z, pv.y, a2));
        a3 = fmaf(w3.x, pv.x, fmaf(w3.z, pv.y, a3));
    }
#pragma unroll 4
    for (int j = j0 + PRE + threadIdx.x; j < j1; j += 256) {
        float2 pv = __ldg(&P2[j]);
        float4 w0 = __ldcs(&Wr0[j]);
        float4 w1 = __ldcs(&Wr1[j]);
        float4 w2 = __ldcs(&Wr2[j]);
        float4 w3 = __ldcs(&Wr3[j]);
        a0 = fmaf(w0.x, pv.x, fmaf(w0.z, pv.y, a0));
        a1 = fmaf(w1.x, pv.x, fmaf(w1.z, pv.y, a1));
        a2 = fmaf(w2.x, pv.x, fmaf(w2.z, pv.y, a2));
        a3 = fmaf(w3.x, pv.x, fmaf(w3.z, pv.y, a3));
    }
#pragma unroll
    for (int o = 16; o; o >>= 1) {
        a0 += __shfl_down_sync(0xffffffffu, a0, o);
        a1 += __shfl_down_sync(0xffffffffu, a1, o);
        a2 += __shfl_down_sync(0xffffffffu, a2, o);
        a3 += __shfl_down_sync(0xffffffffu, a3, o);
    }
    __shared__ float sh[8][ROWS_PB];
    if ((threadIdx.x & 31) == 0) {
        int w = threadIdx.x >> 5;
        sh[w][0] = a0; sh[w][1] = a1; sh[w][2] = a2; sh[w][3] = a3;
    }
    __syncthreads();
    if (threadIdx.x < ROWS_PB) {
        float s = 0.f;
#pragma unroll
        for (int w = 0; w < 8; w++) s += sh[w][threadIdx.x];
        atomicAdd(&out[nt*512 + r0 + threadIdx.x], s);
    }
}

// ---------------------------------------------------------------------------
extern "C" void kernel_launch(void* const* d_in, const int* in_sizes, int n_in,
                              void* d_out, int out_size) {
    const float* xSB = (const float*)d_in[0];
    const float* xPQ = (const float*)d_in[1];
    const float* xPV = (const float*)d_in[2];
    const float* xNB = (const float*)d_in[3];
    const int*   ei  = (const int*)d_in[4];
    const float* ea  = (const float*)d_in[5];

    const float *Wq, *Wk, *Wv, *We, *Ws, *bq, *bk, *bv, *bs;
    if (in_sizes[7] == LNUM*ETN*HD) {
        Wq = (const float*)d_in[6];  bq = (const float*)d_in[7];
        Wk = (const float*)d_in[8];  bk = (const float*)d_in[9];
        Wv = (const float*)d_in[10]; bv = (const float*)d_in[11];
        We = (const float*)d_in[12];
        Ws = (const float*)d_in[13]; bs = (const float*)d_in[14];
    } else {
        Wq = (const float*)d_in[6];
        Wk = (const float*)d_in[7];
        Wv = (const float*)d_in[8];
        We = (const float*)d_in[9];
        Ws = (const float*)d_in[10];
        bq = (const float*)d_in[11];
        bk = (const float*)d_in[12];
        bv = (const float*)d_in[13];
        bs = (const float*)d_in[14];
    }
    const float* fcW_SB = (const float*)d_in[15];
    const float* fcb_SB = (const float*)d_in[16];
    const float* fcW_PQ = (const float*)d_in[17];
    const float* fcb_PQ = (const float*)d_in[18];
    const float* fcW_PV = (const float*)d_in[19];
    const float* fcb_PV = (const float*)d_in[20];
    const float* fcW_NB = (const float*)d_in[21];
    const float* fcb_NB = (const float*)d_in[22];
    float* out = (float*)d_out;

    dim3 eg(NS, NPAIR);
    edge_sweep_kernel<<<eg, 256>>>(xSB, xPQ, xPV, xNB, ei, ea,
                                   Wq, bq, Wk, bk, Wv, bv, We, Ws, bs,
                                   fcb_SB, fcb_PQ, fcb_PV, fcb_NB, out);

    // fc with programmatic dependent launch: overlap W prefetch with edge phase
    cudaLaunchConfig_t cfg = {};
    cfg.gridDim = dim3(7040, 1, 1);
    cfg.blockDim = dim3(256, 1, 1);
    cfg.dynamicSmemBytes = 0;
    cfg.stream = 0;
    cudaLaunchAttribute attrs[1];
    attrs[0].id = cudaLaunchAttributeProgrammaticStreamSerialization;
    attrs[0].val.programmaticStreamSerializationAllowed = 1;
    cfg.attrs = attrs;
    cfg.numAttrs = 1;
    cudaLaunchKernelEx(&cfg, fc_kernel, fcW_SB, fcW_PQ, fcW_PV, fcW_NB, out);
}

// round 16
// speedup vs baseline: 1.3300x; 1.3300x over previous
#include <cuda_runtime.h>
#include <cuda_bf16.h>

// Problem constants
#define HD   128
#define LNUM 2
#define NN   256
#define EE   10000
#define ETN  11
#define NPAIR (LNUM*ETN)          // 22
#define TOTE (NPAIR*EE)           // 220000
#define NS   10                   // splits per pair
#define GPS  250                  // int4 edge-groups per split (1000 edges)
#define CH   2000                 // float4 columns per fc chunk
#define ROWS_PB 4

// EDGE_TYPES src/dst as node-type ids: 0=SB,1=PQ,2=PV,3=NB
__constant__ int c_src[ETN] = {0,2,3,1,1,1,2,3,2,1,3};
__constant__ int c_dst[ETN] = {1,1,1,3,0,2,3,2,2,1,3};
// P buffer offset per pair p=l*11+t (concat: [SB|PQ|PV|NB], (l,t) order within dst)
__constant__ int c_pairOff[NPAIR] = {
  20000, 30000, 40000, 160000, 0, 100000, 170000, 110000, 120000, 50000, 180000,
  60000, 70000, 80000, 190000, 10000, 130000, 200000, 140000, 150000, 90000, 210000
};
// fc geometry per node type
__constant__ int c_nf4[4]    = {10000, 40000, 30000, 30000};  // fan_in/4
__constant__ int c_poff[4]   = {0, 20000, 100000, 160000};    // P offset (float2 units)
__constant__ int c_chunks[4] = {5, 20, 15, 15};               // nf4/CH
__constant__ int c_bcum[5]   = {0, 640, 3200, 5120, 7040};    // 128*chunks cumulative

// Scratch (device globals; no allocations allowed)
__device__ __align__(16) float g_P[TOTE];
// per-(pair,split) partial segment state: [NPAIR*NS][NN]
__device__ float g_pden[NPAIR*NS*NN];
__device__ float g_pnum[NPAIR*NS*NN];
__device__ int   g_pfirst[NPAIR*NS*NN];

__device__ __forceinline__ const float* selx(int nt, const float* a, const float* b,
                                             const float* c, const float* d) {
    return nt == 0 ? a : (nt == 1 ? b : (nt == 2 ? c : d));
}

// ---------------------------------------------------------------------------
// Edge sweep: grid (NS, NPAIR) x 256 threads. Each block handles 1000 edges of
// one pair. Edge index/attr loads are issued at kernel entry so their DRAM
// latency overlaps the coef phase. Single sweep: logit -> exp (no max
// subtraction: logits ~ N(0,1), overflow-safe; softmax ratios scale-exact),
// vsum, skip-P writeout; smem segment accumulation; partials flushed to L2.
// ---------------------------------------------------------------------------
__global__ void __launch_bounds__(256) edge_sweep_kernel(
    const float* __restrict__ xSB, const float* __restrict__ xPQ,
    const float* __restrict__ xPV, const float* __restrict__ xNB,
    const int* __restrict__ ei, const float* __restrict__ ea,
    const float* __restrict__ Wq, const float* __restrict__ bq,
    const float* __restrict__ Wk, const float* __restrict__ bk,
    const float* __restrict__ Wv, const float* __restrict__ bv,
    const float* __restrict__ We,
    const float* __restrict__ Ws, const float* __restrict__ bs) {
    const int split = blockIdx.x;
    const int p = blockIdx.y;
    const int t = p % ETN;
    const int tid = threadIdx.x;

    __shared__ float C[23];
    __shared__ float red[4][23];
    __shared__ float sm_den[NN];
    __shared__ float sm_num[NN];
    __shared__ int   sm_first[NN];

    // ---- prefetch this thread's edge data (overlaps coef phase latency) ----
    const int g = split*GPS + tid;          // valid when tid < GPS
    const bool active = (tid < GPS);
    int4 sv, dv;
    float4 eA, eB;
    if (active) {
        const int4* eis4 = (const int4*)(ei + (t*2+0)*EE);
        const int4* eid4 = (const int4*)(ei + (t*2+1)*EE);
        const float4* eat4 = (const float4*)(ea + (size_t)t*EE*2);
        sv = eis4[g];
        dv = eid4[g];
        eA = eat4[g*2+0];
        eB = eat4[g*2+1];
    }

    // ---- coef: collapse H=128 weights to 23 scalars ----
    if (tid < HD) {
        int h = tid;
        float wq0 = Wq[(p*2+0)*HD+h], wq1 = Wq[(p*2+1)*HD+h], bqv = bq[p*HD+h];
        float wk0 = Wk[(p*2+0)*HD+h], wk1 = Wk[(p*2+1)*HD+h], bkv = bk[p*HD+h];
        float we0 = We[(p*2+0)*HD+h], we1 = We[(p*2+1)*HD+h];
        float wv0 = Wv[(p*2+0)*HD+h], wv1 = Wv[(p*2+1)*HD+h], bvv = bv[p*HD+h];
        float ws0 = Ws[(p*2+0)*HD+h], ws1 = Ws[(p*2+1)*HD+h], bsv = bs[p*HD+h];
        float av[3] = {wq0, wq1, bqv};
        float bb[5] = {wk0, wk1, bkv, we0, we1};
        float vals[23];
#pragma unroll
        for (int a = 0; a < 3; a++)
#pragma unroll
            for (int b = 0; b < 5; b++) vals[a*5+b] = av[a]*bb[b];
        vals[15]=wv0; vals[16]=wv1; vals[17]=bvv; vals[18]=we0; vals[19]=we1;
        vals[20]=ws0; vals[21]=ws1; vals[22]=bsv;
        int lane = h & 31, w = h >> 5;
#pragma unroll
        for (int i = 0; i < 23; i++) {
            float v = vals[i];
#pragma unroll
            for (int o = 16; o; o >>= 1) v += __shfl_down_sync(0xffffffffu, v, o);
            if (lane == 0) red[w][i] = v;
        }
    }
    sm_den[tid] = 0.f;
    sm_num[tid] = 0.f;
    sm_first[tid] = 0x7fffffff;
    __syncthreads();
    if (tid < 23) C[tid] = red[0][tid] + red[1][tid] + red[2][tid] + red[3][tid];
    __syncthreads();

    const float* xsrc = selx(c_src[t], xSB, xPQ, xPV, xNB);
    const float* xdst = selx(c_dst[t], xSB, xPQ, xPV, xNB);

    // ---- single sweep over this split's 250 groups (1000 edges) ----
    if (active) {
        int ss[4] = {sv.x, sv.y, sv.z, sv.w};
        int dd[4] = {dv.x, dv.y, dv.z, dv.w};
        float e0[4] = {eA.x, eA.z, eB.x, eB.z};
        float e1[4] = {eA.y, eA.w, eB.y, eB.w};
        float pv[4];
#pragma unroll
        for (int k = 0; k < 4; k++) {
            float2 xsv = *(const float2*)(xsrc + ss[k]*4 + 2);
            float2 xtv = *(const float2*)(xdst + dd[k]*4 + 2);
            float xs0 = xsv.x, xs1 = xsv.y;
            float xt0 = xtv.x, xt1 = xtv.y;
            float r0 = C[0]*xs0 + C[1]*xs1 + C[2] + C[3]*e0[k] + C[4]*e1[k];
            float r1 = C[5]*xs0 + C[6]*xs1 + C[7] + C[8]*e0[k] + C[9]*e1[k];
            float r2 = C[10]*xs0 + C[11]*xs1 + C[12] + C[13]*e0[k] + C[14]*e1[k];
            float logit = (xt0*r0 + xt1*r1 + r2) * 0.08838834764831845f; // 1/sqrt(128)
            float ex = __expf(logit);
            float vs = xs0*C[15] + xs1*C[16] + C[17] + e0[k]*C[18] + e1[k]*C[19];
            atomicAdd(&sm_den[dd[k]], ex);
            atomicAdd(&sm_num[dd[k]], ex * vs);
            atomicMin(&sm_first[dd[k]], g*4 + k);
            pv[k] = xt0*C[20] + xt1*C[21] + C[22];   // skip term only
        }
        ((float4*)(g_P + c_pairOff[p]))[g] = make_float4(pv[0], pv[1], pv[2], pv[3]);
    }
    __syncthreads();

    // ---- flush per-split partials (full 256 slots; no global init needed) ----
    int base = (p*NS + split)*NN + tid;
    g_pden[base] = sm_den[tid];
    g_pnum[base] = sm_num[tid];
    g_pfirst[base] = sm_first[tid];
}

// ---------------------------------------------------------------------------
// Merge: 22 blocks x 256 threads. Sum the 10 split partials per segment and
// add num/den at the first edge position of each dst node. Blocks p<8 also
// initialize out with the bias (fc then atomicAdds its partials into out).
// ---------------------------------------------------------------------------
__global__ void __launch_bounds__(256) edge_merge_kernel(
    const float* __restrict__ B0, const float* __restrict__ B1,
    const float* __restrict__ B2, const float* __restrict__ B3,
    float* __restrict__ out) {
    int p = blockIdx.x;
    int s = threadIdx.x;
    float den = 0.f, num = 0.f;
    int first = 0x7fffffff;
    int base = p*NS*NN + s;
#pragma unroll
    for (int sp = 0; sp < NS; sp++) {
        den += g_pden[base + sp*NN];
        num += g_pnum[base + sp*NN];
        first = min(first, g_pfirst[base + sp*NN]);
    }
    if (first != 0x7fffffff)
        g_P[c_pairOff[p] + first] += num / den;
    if (p < 8) {   // init out = bias
        int i = p*256 + s;
        int nt = i >> 9, r = i & 511;
        const float* B = selx(nt, B0, B1, B2, B3);
        out[i] = B[r];
    }
}

// ---------------------------------------------------------------------------
// FC matvec, split-K: each block = 4 rows x one 2000-float4 column chunk.
// 7040 blocks = 5.95 waves of 1184 concurrent -> last wave 94.6% full.
// Partials atomicAdd directly into out (pre-set to bias). W streamed with
// __ldcs (read-once) so L2 keeps P resident. unroll 8 front-batches ~all of
// the chunk's loads for maximum memory-level parallelism.
// ---------------------------------------------------------------------------
__global__ void __launch_bounds__(256) fc_kernel(
    const float* __restrict__ W0, const float* __restrict__ W1,
    const float* __restrict__ W2, const float* __restrict__ W3,
    float* __restrict__ out) {
    int bid = blockIdx.x;
    int nt = 3;
    if (bid < c_bcum[1]) nt = 0;
    else if (bid < c_bcum[2]) nt = 1;
    else if (bid < c_bcum[3]) nt = 2;
    int local = bid - c_bcum[nt];
    int nchunk = c_chunks[nt];
    int rg = local / nchunk;       // 0..127
    int ch = local % nchunk;
    int nf4 = c_nf4[nt];
    int r0 = rg * ROWS_PB;
    const float* W = selx(nt, W0, W1, W2, W3);
    const float4* __restrict__ Wr0 = (const float4*)W + (size_t)(r0+0) * nf4;
    const float4* __restrict__ Wr1 = (const float4*)W + (size_t)(r0+1) * nf4;
    const float4* __restrict__ Wr2 = (const float4*)W + (size_t)(r0+2) * nf4;
    const float4* __restrict__ Wr3 = (const float4*)W + (size_t)(r0+3) * nf4;
    const float2* __restrict__ P2 = (const float2*)(g_P + c_poff[nt]);

    int j0 = ch * CH;
    int j1 = j0 + CH;
    float a0 = 0.f, a1 = 0.f, a2 = 0.f, a3 = 0.f;
#pragma unroll 8
    for (int j = j0 + threadIdx.x; j < j1; j += 256) {
        float2 pv = __ldg(&P2[j]);
        float4 w0 = __ldcs(&Wr0[j]);
        float4 w1 = __ldcs(&Wr1[j]);
        float4 w2 = __ldcs(&Wr2[j]);
        float4 w3 = __ldcs(&Wr3[j]);
        a0 = fmaf(w0.x, pv.x, fmaf(w0.z, pv.y, a0));
        a1 = fmaf(w1.x, pv.x, fmaf(w1.z, pv.y, a1));
        a2 = fmaf(w2.x, pv.x, fmaf(w2.z, pv.y, a2));
        a3 = fmaf(w3.x, pv.x, fmaf(w3.z, pv.y, a3));
    }
#pragma unroll
    for (int o = 16; o; o >>= 1) {
        a0 += __shfl_down_sync(0xffffffffu, a0, o);
        a1 += __shfl_down_sync(0xffffffffu, a1, o);
        a2 += __shfl_down_sync(0xffffffffu, a2, o);
        a3 += __shfl_down_sync(0xffffffffu, a3, o);
    }
    __shared__ float sh[8][ROWS_PB];
    if ((threadIdx.x & 31) == 0) {
        int w = threadIdx.x >> 5;
        sh[w][0] = a0; sh[w][1] = a1; sh[w][2] = a2; sh[w][3] = a3;
    }
    __syncthreads();
    if (threadIdx.x < ROWS_PB) {
        float s = 0.f;
#pragma unroll
        for (int w = 0; w < 8; w++) s += sh[w][threadIdx.x];
        atomicAdd(&out[nt*512 + r0 + threadIdx.x], s);
    }
}

// ---------------------------------------------------------------------------
extern "C" void kernel_launch(void* const* d_in, const int* in_sizes, int n_in,
                              void* d_out, int out_size) {
    const float* xSB = (const float*)d_in[0];
    const float* xPQ = (const float*)d_in[1];
    const float* xPV = (const float*)d_in[2];
    const float* xNB = (const float*)d_in[3];
    const int*   ei  = (const int*)d_in[4];
    const float* ea  = (const float*)d_in[5];

    const float *Wq, *Wk, *Wv, *We, *Ws, *bq, *bk, *bv, *bs;
    if (in_sizes[7] == LNUM*ETN*HD) {
        Wq = (const float*)d_in[6];  bq = (const float*)d_in[7];
        Wk = (const float*)d_in[8];  bk = (const float*)d_in[9];
        Wv = (const float*)d_in[10]; bv = (const float*)d_in[11];
        We = (const float*)d_in[12];
        Ws = (const float*)d_in[13]; bs = (const float*)d_in[14];
    } else {
        Wq = (const float*)d_in[6];
        Wk = (const float*)d_in[7];
        Wv = (const float*)d_in[8];
        We = (const float*)d_in[9];
        Ws = (const float*)d_in[10];
        bq = (const float*)d_in[11];
        bk = (const float*)d_in[12];
        bv = (const float*)d_in[13];
        bs = (const float*)d_in[14];
    }
    const float* fcW_SB = (const float*)d_in[15];
    const float* fcb_SB = (const float*)d_in[16];
    const float* fcW_PQ = (const float*)d_in[17];
    const float* fcb_PQ = (const float*)d_in[18];
    const float* fcW_PV = (const float*)d_in[19];
    const float* fcb_PV = (const float*)d_in[20];
    const float* fcW_NB = (const float*)d_in[21];
    const float* fcb_NB = (const float*)d_in[22];
    float* out = (float*)d_out;

    dim3 eg(NS, NPAIR);
    edge_sweep_kernel<<<eg, 256>>>(xSB, xPQ, xPV, xNB, ei, ea,
                                   Wq, bq, Wk, bk, Wv, bv, We, Ws, bs);
    edge_merge_kernel<<<NPAIR, 256>>>(fcb_SB, fcb_PQ, fcb_PV, fcb_NB, out);
    fc_kernel<<<7040, 256>>>(fcW_SB, fcW_PQ, fcW_PV, fcW_NB, out);
}

// round 17
// speedup vs baseline: 1.4317x; 1.0765x over previous
#include <cuda_runtime.h>
#include <cuda_bf16.h>

// Problem constants
#define HD   128
#define LNUM 2
#define NN   256
#define EE   10000
#define ETN  11
#define NPAIR (LNUM*ETN)          // 22
#define TOTE (NPAIR*EE)           // 220000
#define NS   10                   // splits per pair
#define GPS  250                  // int4 edge-groups per split (1000 edges)
#define CH   2000                 // float4 columns per fc chunk
#define ROWS_PB 4

// EDGE_TYPES src/dst as node-type ids: 0=SB,1=PQ,2=PV,3=NB
__constant__ int c_src[ETN] = {0,2,3,1,1,1,2,3,2,1,3};
__constant__ int c_dst[ETN] = {1,1,1,3,0,2,3,2,2,1,3};
// P buffer offset per pair p=l*11+t (concat: [SB|PQ|PV|NB], (l,t) order within dst)
__constant__ int c_pairOff[NPAIR] = {
  20000, 30000, 40000, 160000, 0, 100000, 170000, 110000, 120000, 50000, 180000,
  60000, 70000, 80000, 190000, 10000, 130000, 200000, 140000, 150000, 90000, 210000
};
// fc geometry per node type
__constant__ int c_nf4[4]    = {10000, 40000, 30000, 30000};  // fan_in/4
__constant__ int c_poff[4]   = {0, 20000, 100000, 160000};    // P offset (float2 units)
__constant__ int c_chunks[4] = {5, 20, 15, 15};               // nf4/CH
__constant__ int c_bcum[5]   = {0, 640, 3200, 5120, 7040};    // 128*chunks cumulative

// Scratch (device globals; no allocations allowed)
__device__ __align__(16) float g_P[TOTE];
// per-(pair,split) partial segment state: [NPAIR*NS][NN]
__device__ float g_pden[NPAIR*NS*NN];
__device__ float g_pnum[NPAIR*NS*NN];
__device__ int   g_pfirst[NPAIR*NS*NN];

__device__ __forceinline__ const float* selx(int nt, const float* a, const float* b,
                                             const float* c, const float* d) {
    return nt == 0 ? a : (nt == 1 ? b : (nt == 2 ? c : d));
}

// ---------------------------------------------------------------------------
// Edge sweep: grid (NS, NPAIR) x 256 threads. Each block handles 1000 edges of
// one pair. Edge index/attr loads are issued at kernel entry so their DRAM
// latency overlaps the coef phase. Single sweep: logit -> exp (no max
// subtraction: logits ~ N(0,1), overflow-safe; softmax ratios scale-exact),
// vsum, skip-P writeout; smem segment accumulation; partials flushed to L2.
// ---------------------------------------------------------------------------
__global__ void __launch_bounds__(256) edge_sweep_kernel(
    const float* __restrict__ xSB, const float* __restrict__ xPQ,
    const float* __restrict__ xPV, const float* __restrict__ xNB,
    const int* __restrict__ ei, const float* __restrict__ ea,
    const float* __restrict__ Wq, const float* __restrict__ bq,
    const float* __restrict__ Wk, const float* __restrict__ bk,
    const float* __restrict__ Wv, const float* __restrict__ bv,
    const float* __restrict__ We,
    const float* __restrict__ Ws, const float* __restrict__ bs) {
    const int split = blockIdx.x;
    const int p = blockIdx.y;
    const int t = p % ETN;
    const int tid = threadIdx.x;

    __shared__ float C[23];
    __shared__ float red[4][23];
    __shared__ float sm_den[NN];
    __shared__ float sm_num[NN];
    __shared__ int   sm_first[NN];

    // ---- prefetch this thread's edge data (overlaps coef phase latency) ----
    const int g = split*GPS + tid;          // valid when tid < GPS
    const bool active = (tid < GPS);
    int4 sv, dv;
    float4 eA, eB;
    if (active) {
        const int4* eis4 = (const int4*)(ei + (t*2+0)*EE);
        const int4* eid4 = (const int4*)(ei + (t*2+1)*EE);
        const float4* eat4 = (const float4*)(ea + (size_t)t*EE*2);
        sv = eis4[g];
        dv = eid4[g];
        eA = eat4[g*2+0];
        eB = eat4[g*2+1];
    }

    // ---- coef: collapse H=128 weights to 23 scalars ----
    if (tid < HD) {
        int h = tid;
        float wq0 = Wq[(p*2+0)*HD+h], wq1 = Wq[(p*2+1)*HD+h], bqv = bq[p*HD+h];
        float wk0 = Wk[(p*2+0)*HD+h], wk1 = Wk[(p*2+1)*HD+h], bkv = bk[p*HD+h];
        float we0 = We[(p*2+0)*HD+h], we1 = We[(p*2+1)*HD+h];
        float wv0 = Wv[(p*2+0)*HD+h], wv1 = Wv[(p*2+1)*HD+h], bvv = bv[p*HD+h];
        float ws0 = Ws[(p*2+0)*HD+h], ws1 = Ws[(p*2+1)*HD+h], bsv = bs[p*HD+h];
        float av[3] = {wq0, wq1, bqv};
        float bb[5] = {wk0, wk1, bkv, we0, we1};
        float vals[23];
#pragma unroll
        for (int a = 0; a < 3; a++)
#pragma unroll
            for (int b = 0; b < 5; b++) vals[a*5+b] = av[a]*bb[b];
        vals[15]=wv0; vals[16]=wv1; vals[17]=bvv; vals[18]=we0; vals[19]=we1;
        vals[20]=ws0; vals[21]=ws1; vals[22]=bsv;
        int lane = h & 31, w = h >> 5;
#pragma unroll
        for (int i = 0; i < 23; i++) {
            float v = vals[i];
#pragma unroll
            for (int o = 16; o; o >>= 1) v += __shfl_down_sync(0xffffffffu, v, o);
            if (lane == 0) red[w][i] = v;
        }
    }
    sm_den[tid] = 0.f;
    sm_num[tid] = 0.f;
    sm_first[tid] = 0x7fffffff;
    __syncthreads();
    if (tid < 23) C[tid] = red[0][tid] + red[1][tid] + red[2][tid] + red[3][tid];
    __syncthreads();

    const float* xsrc = selx(c_src[t], xSB, xPQ, xPV, xNB);
    const float* xdst = selx(c_dst[t], xSB, xPQ, xPV, xNB);

    // ---- single sweep over this split's 250 groups (1000 edges) ----
    if (active) {
        int ss[4] = {sv.x, sv.y, sv.z, sv.w};
        int dd[4] = {dv.x, dv.y, dv.z, dv.w};
        float e0[4] = {eA.x, eA.z, eB.x, eB.z};
        float e1[4] = {eA.y, eA.w, eB.y, eB.w};
        float pv[4];
#pragma unroll
        for (int k = 0; k < 4; k++) {
            float2 xsv = *(const float2*)(xsrc + ss[k]*4 + 2);
            float2 xtv = *(const float2*)(xdst + dd[k]*4 + 2);
            float xs0 = xsv.x, xs1 = xsv.y;
            float xt0 = xtv.x, xt1 = xtv.y;
            float r0 = C[0]*xs0 + C[1]*xs1 + C[2] + C[3]*e0[k] + C[4]*e1[k];
            float r1 = C[5]*xs0 + C[6]*xs1 + C[7] + C[8]*e0[k] + C[9]*e1[k];
            float r2 = C[10]*xs0 + C[11]*xs1 + C[12] + C[13]*e0[k] + C[14]*e1[k];
            float logit = (xt0*r0 + xt1*r1 + r2) * 0.08838834764831845f; // 1/sqrt(128)
            float ex = __expf(logit);
            float vs = xs0*C[15] + xs1*C[16] + C[17] + e0[k]*C[18] + e1[k]*C[19];
            atomicAdd(&sm_den[dd[k]], ex);
            atomicAdd(&sm_num[dd[k]], ex * vs);
            atomicMin(&sm_first[dd[k]], g*4 + k);
            pv[k] = xt0*C[20] + xt1*C[21] + C[22];   // skip term only
        }
        ((float4*)(g_P + c_pairOff[p]))[g] = make_float4(pv[0], pv[1], pv[2], pv[3]);
    }
    __syncthreads();

    // ---- flush per-split partials (full 256 slots; no global init needed) ----
    int base = (p*NS + split)*NN + tid;
    g_pden[base] = sm_den[tid];
    g_pnum[base] = sm_num[tid];
    g_pfirst[base] = sm_first[tid];
}

// ---------------------------------------------------------------------------
// Merge: 22 blocks x 256 threads. Sum the 10 split partials per segment and
// add num/den at the first edge position of each dst node. Blocks p<8 also
// initialize out with the bias (fc then atomicAdds its partials into out).
// ---------------------------------------------------------------------------
__global__ void __launch_bounds__(256) edge_merge_kernel(
    const float* __restrict__ B0, const float* __restrict__ B1,
    const float* __restrict__ B2, const float* __restrict__ B3,
    float* __restrict__ out) {
    int p = blockIdx.x;
    int s = threadIdx.x;
    float den = 0.f, num = 0.f;
    int first = 0x7fffffff;
    int base = p*NS*NN + s;
#pragma unroll
    for (int sp = 0; sp < NS; sp++) {
        den += g_pden[base + sp*NN];
        num += g_pnum[base + sp*NN];
        first = min(first, g_pfirst[base + sp*NN]);
    }
    if (first != 0x7fffffff)
        g_P[c_pairOff[p] + first] += num / den;
    if (p < 8) {   // init out = bias
        int i = p*256 + s;
        int nt = i >> 9, r = i & 511;
        const float* B = selx(nt, B0, B1, B2, B3);
        out[i] = B[r];
    }
}

// ---------------------------------------------------------------------------
// FC matvec, split-K: each block = 4 rows x one 2000-float4 column chunk.
// 7040 blocks = 5.95 waves of 1184 concurrent -> last wave 94.6% full.
// Partials atomicAdd directly into out (pre-set to bias). W streamed with
// __ldcs (read-once) so L2 keeps P resident.
// ---------------------------------------------------------------------------
__global__ void __launch_bounds__(256) fc_kernel(
    const float* __restrict__ W0, const float* __restrict__ W1,
    const float* __restrict__ W2, const float* __restrict__ W3,
    float* __restrict__ out) {
    int bid = blockIdx.x;
    int nt = 3;
    if (bid < c_bcum[1]) nt = 0;
    else if (bid < c_bcum[2]) nt = 1;
    else if (bid < c_bcum[3]) nt = 2;
    int local = bid - c_bcum[nt];
    int nchunk = c_chunks[nt];
    int rg = local / nchunk;       // 0..127
    int ch = local % nchunk;
    int nf4 = c_nf4[nt];
    int r0 = rg * ROWS_PB;
    const float* W = selx(nt, W0, W1, W2, W3);
    const float4* __restrict__ Wr0 = (const float4*)W + (size_t)(r0+0) * nf4;
    const float4* __restrict__ Wr1 = (const float4*)W + (size_t)(r0+1) * nf4;
    const float4* __restrict__ Wr2 = (const float4*)W + (size_t)(r0+2) * nf4;
    const float4* __restrict__ Wr3 = (const float4*)W + (size_t)(r0+3) * nf4;
    const float2* __restrict__ P2 = (const float2*)(g_P + c_poff[nt]);

    int j0 = ch * CH;
    int j1 = j0 + CH;
    float a0 = 0.f, a1 = 0.f, a2 = 0.f, a3 = 0.f;
#pragma unroll 4
    for (int j = j0 + threadIdx.x; j < j1; j += 256) {
        float2 pv = __ldg(&P2[j]);
        float4 w0 = __ldcs(&Wr0[j]);
        float4 w1 = __ldcs(&Wr1[j]);
        float4 w2 = __ldcs(&Wr2[j]);
        float4 w3 = __ldcs(&Wr3[j]);
        a0 = fmaf(w0.x, pv.x, fmaf(w0.z, pv.y, a0));
        a1 = fmaf(w1.x, pv.x, fmaf(w1.z, pv.y, a1));
        a2 = fmaf(w2.x, pv.x, fmaf(w2.z, pv.y, a2));
        a3 = fmaf(w3.x, pv.x, fmaf(w3.z, pv.y, a3));
    }
#pragma unroll
    for (int o = 16; o; o >>= 1) {
        a0 += __shfl_down_sync(0xffffffffu, a0, o);
        a1 += __shfl_down_sync(0xffffffffu, a1, o);
        a2 += __shfl_down_sync(0xffffffffu, a2, o);
        a3 += __shfl_down_sync(0xffffffffu, a3, o);
    }
    __shared__ float sh[8][ROWS_PB];
    if ((threadIdx.x & 31) == 0) {
        int w = threadIdx.x >> 5;
        sh[w][0] = a0; sh[w][1] = a1; sh[w][2] = a2; sh[w][3] = a3;
    }
    __syncthreads();
    if (threadIdx.x < ROWS_PB) {
        float s = 0.f;
#pragma unroll
        for (int w = 0; w < 8; w++) s += sh[w][threadIdx.x];
        atomicAdd(&out[nt*512 + r0 + threadIdx.x], s);
    }
}

// ---------------------------------------------------------------------------
extern "C" void kernel_launch(void* const* d_in, const int* in_sizes, int n_in,
                              void* d_out, int out_size) {
    const float* xSB = (const float*)d_in[0];
    const float* xPQ = (const float*)d_in[1];
    const float* xPV = (const float*)d_in[2];
    const float* xNB = (const float*)d_in[3];
    const int*   ei  = (const int*)d_in[4];
    const float* ea  = (const float*)d_in[5];

    const float *Wq, *Wk, *Wv, *We, *Ws, *bq, *bk, *bv, *bs;
    if (in_sizes[7] == LNUM*ETN*HD) {
        Wq = (const float*)d_in[6];  bq = (const float*)d_in[7];
        Wk = (const float*)d_in[8];  bk = (const float*)d_in[9];
        Wv = (const float*)d_in[10]; bv = (const float*)d_in[11];
        We = (const float*)d_in[12];
        Ws = (const float*)d_in[13]; bs = (const float*)d_in[14];
    } else {
        Wq = (const float*)d_in[6];
        Wk = (const float*)d_in[7];
        Wv = (const float*)d_in[8];
        We = (const float*)d_in[9];
        Ws = (const float*)d_in[10];
        bq = (const float*)d_in[11];
        bk = (const float*)d_in[12];
        bv = (const float*)d_in[13];
        bs = (const float*)d_in[14];
    }
    const float* fcW_SB = (const float*)d_in[15];
    const float* fcb_SB = (const float*)d_in[16];
    const float* fcW_PQ = (const float*)d_in[17];
    const float* fcb_PQ = (const float*)d_in[18];
    const float* fcW_PV = (const float*)d_in[19];
    const float* fcb_PV = (const float*)d_in[20];
    const float* fcW_NB = (const float*)d_in[21];
    const float* fcb_NB = (const float*)d_in[22];
    float* out = (float*)d_out;

    dim3 eg(NS, NPAIR);
    edge_sweep_kernel<<<eg, 256>>>(xSB, xPQ, xPV, xNB, ei, ea,
                                   Wq, bq, Wk, bk, Wv, bv, We, Ws, bs);
    edge_merge_kernel<<<NPAIR, 256>>>(fcb_SB, fcb_PQ, fcb_PV, fcb_NB, out);
    fc_kernel<<<7040, 256>>>(fcW_SB, fcW_PQ, fcW_PV, fcW_NB, out);
}